// round 16
// baseline (speedup 1.0000x reference)
#include <cuda_runtime.h>
#include <math.h>
#include <stdint.h>

// ---------------------------------------------------------------------------
// RelationalPathGNN — round 16
//   * GEMM: 4-stage A-gather pipeline (prefetch distance 3); B fragments read
//     directly from L2 via __ldg (removed from the commit-group wait path)
//   * otherwise identical to round-15 champion
// ---------------------------------------------------------------------------

namespace {
constexpr int N_   = 20000;
constexpr int E_   = 160000;
constexpr int EMB_ = 64;
constexpr int HID_ = 128;
constexpr int R_   = 8;
constexpr int BM   = 128;                       // rows per GEMM tile
constexpr int MT   = E_ / BM + R_;              // 1258 worst-case tiles
constexpr int SCAN_BS = 512;
constexpr int SCAN_NB = (N_ + SCAN_BS - 1) / SCAN_BS;   // 40
constexpr int WT1 = R_ * 6 * HID_ * 32;         // W1 frag floats (196608)
constexpr int WT2 = R_ * 8 * EMB_ * 32;         // W2 frag floats (131072)
constexpr int SL1F = 2 * HID_ * 32;             // L1 frag floats (8192)
constexpr int SL2F = 2 * EMB_ * 32;             // L2 frag floats (4096)
}

// ------------------------- scratch (static device) -------------------------
__device__ float    g_m[(size_t)E_ * HID_];     // edge messages (fp32, dst-CSR)
__device__ float    g_z[E_];                    // logits, dst-CSR order
__device__ float    g_hn[(size_t)N_ * HID_];    // degree-scaled h
__device__ float    g_Wt1[WT1];                 // W1 fragment-major, rna tf32
__device__ float    g_Wt2[WT2];                 // W2 fragment-major, rna tf32
__device__ float    g_Lf1[SL1F];                // L1 fragment-major, rna tf32
__device__ float    g_Lf2[SL2F];                // L2 fragment-major, rna tf32
__device__ float    g_sl1[(size_t)N_ * HID_];   // self-loop ne@L1
__device__ float    g_sl2[(size_t)N_ * EMB_];   // self-loop ne@L2
__device__ float    g_inv_out[N_], g_inv_in[N_];
__device__ int      g_outdeg_i[N_], g_indeg_i[N_];
__device__ int      g_cnt[R_], g_off[R_ + 1], g_cur[R_];
__device__ int      g_perm[E_ + R_ * BM];
__device__ int      g_doff[N_], g_dcur[N_], g_dtmp[N_], g_dblk[SCAN_NB];
__device__ int      g_epos[E_];                 // edge -> dst-CSR position
__device__ float    g_zn1[N_], g_zn2[N_];

// ------------------------------ helpers ------------------------------------
__device__ __forceinline__ uint32_t tf32r(float x) {
    uint32_t u;
    asm("cvt.rna.tf32.f32 %0, %1;" : "=r"(u) : "f"(x));
    return u;
}
__device__ __forceinline__ uint32_t smem_u32(const void* p) {
    uint32_t a;
    asm("{ .reg .u64 t; cvta.to.shared.u64 t, %1; cvt.u32.u64 %0, t; }"
        : "=r"(a) : "l"(p));
    return a;
}
__device__ __forceinline__ void cp_async16(uint32_t daddr, const void* gptr) {
    asm volatile("cp.async.cg.shared.global [%0], [%1], 16;"
                 :: "r"(daddr), "l"(gptr) : "memory");
}
__device__ __forceinline__ void st_cs_f2(float* p, float a, float b) {
    asm volatile("st.global.cs.v2.f32 [%0], {%1, %2};"
                 :: "l"(p), "f"(a), "f"(b) : "memory");
}
__device__ __forceinline__ float4 ld_cs_f4(const float* p) {
    float4 v;
    asm volatile("ld.global.cs.v4.f32 {%0, %1, %2, %3}, [%4];"
                 : "=f"(v.x), "=f"(v.y), "=f"(v.z), "=f"(v.w) : "l"(p));
    return v;
}
__device__ __forceinline__ float2 ld_cs_f2(const float* p) {
    float2 v;
    asm volatile("ld.global.cs.v2.f32 {%0, %1}, [%2];"
                 : "=f"(v.x), "=f"(v.y) : "l"(p));
    return v;
}

// ---- weight bake helper (fragment-major, rna tf32) ----
template <int K, int NOUT>
__device__ __forceinline__ void wfrag_one(const float* __restrict__ W,
                                          float* __restrict__ out, int idx) {
    constexpr int KC = K / 32;
    constexpr int NFH = NOUT / 32;
    int i  = idx % (NOUT * 32);
    int rc = idx / (NOUT * 32);
    int c  = rc % KC, r = rc / KC;
    int f    = i & 3;
    int t    = i >> 2;
    int lane = t & 31;
    int t2   = t >> 5;
    int j    = t2 % NFH;
    int t3   = t2 / NFH;
    int wc   = t3 & 1;
    int ks   = t3 >> 1;
    int g = lane >> 2, q = lane & 3;
    int k   = c * 32 + ks * 8 + q + (f & 1) * 4;
    int col = wc * (NOUT / 2) + (2 * j + (f >> 1)) * 8 + g;
    out[idx] = __uint_as_float(tf32r(W[((size_t)r * K + k) * NOUT + col]));
}

// ------------------------------ prep kernels -------------------------------
__global__ void k_zero_wfrag(const float* __restrict__ W1,
                             const float* __restrict__ W2,
                             const float* __restrict__ L1,
                             const float* __restrict__ L2) {
    int i = blockIdx.x * blockDim.x + threadIdx.x;
    if (i < N_) { g_outdeg_i[i] = 0; g_indeg_i[i] = 0; }
    if (i < R_) g_cnt[i] = 0;
    if (i < WT1)                          wfrag_one<192, 128>(W1, g_Wt1, i);
    else if (i < WT1 + WT2)               wfrag_one<256, 64>(W2, g_Wt2, i - WT1);
    else if (i < WT1 + WT2 + SL1F)        wfrag_one<64, 128>(L1, g_Lf1, i - WT1 - WT2);
    else if (i < WT1 + WT2 + SL1F + SL2F) wfrag_one<64, 64>(L2, g_Lf2, i - WT1 - WT2 - SL1F);
}

__global__ void k_count(const int* __restrict__ src, const int* __restrict__ dst,
                        const int* __restrict__ eid) {
    __shared__ int h[R_];
    int tid = threadIdx.x;
    if (tid < R_) h[tid] = 0;
    __syncthreads();
    int e = blockIdx.x * blockDim.x + tid;
    if (e < E_) {
        atomicAdd(&g_outdeg_i[src[e]], 1);
        atomicAdd(&g_indeg_i[dst[e]], 1);
        atomicAdd(&h[eid[e]], 1);
    }
    __syncthreads();
    if (tid < R_ && h[tid] > 0) atomicAdd(&g_cnt[tid], h[tid]);
}

// ---- parallel dst-CSR scan chain (40 blocks) ----
__global__ void k_scan_blk() {
    __shared__ int sh[SCAN_BS];
    int i = blockIdx.x * SCAN_BS + threadIdx.x;
    int v = (i < N_) ? g_indeg_i[i] : 0;
    sh[threadIdx.x] = v;
    __syncthreads();
    for (int o = 1; o < SCAN_BS; o <<= 1) {
        int t = (threadIdx.x >= o) ? sh[threadIdx.x - o] : 0;
        __syncthreads();
        sh[threadIdx.x] += t;
        __syncthreads();
    }
    if (i < N_) g_dtmp[i] = sh[threadIdx.x] - v;
    if (threadIdx.x == SCAN_BS - 1) g_dblk[blockIdx.x] = sh[SCAN_BS - 1];
}

__global__ void k_scan_top() {
    if (threadIdx.x == 0) {
        int o = 0;
        for (int r = 0; r < R_; r++) {
            g_off[r] = o; g_cur[r] = o;
            o += ((g_cnt[r] + BM - 1) / BM) * BM;
        }
        g_off[R_] = o;
    } else if (threadIdx.x == 32) {
        int a = 0;
        for (int b = 0; b < SCAN_NB; b++) { int t = g_dblk[b]; g_dblk[b] = a; a += t; }
    }
}

// merged (warp-per-node): finish dst scan + normalizers + hn + zn1/zn2 dots
__global__ void k_scan_addnode(const float* __restrict__ ne,
                               const float* __restrict__ A1,
                               const float* __restrict__ A2) {
    int gt = blockIdx.x * blockDim.x + threadIdx.x;
    int n = gt >> 5, lane = gt & 31;
    if (n >= N_) return;
    float so, si;
    if (lane == 0) {
        int o = g_dtmp[n] + g_dblk[n / SCAN_BS];
        g_doff[n] = o; g_dcur[n] = o;
        so = 1.f / sqrtf(fmaxf((float)g_outdeg_i[n], 1.f));
        si = 1.f / sqrtf(fmaxf((float)g_indeg_i[n], 1.f));
        g_inv_out[n] = so; g_inv_in[n] = si;
    }
    so = __shfl_sync(0xffffffffu, so, 0);
    float x0 = ne[(size_t)n * 64 + lane], x1 = ne[(size_t)n * 64 + 32 + lane];
    g_hn[(size_t)n * 64 + lane]      = x0 * so;
    g_hn[(size_t)n * 64 + 32 + lane] = x1 * so;
    float s1 = x0 * A1[lane] + x1 * A1[32 + lane];
    float s2 = x0 * A2[lane] + x1 * A2[32 + lane];
#pragma unroll
    for (int o = 16; o; o >>= 1) {
        s1 += __shfl_xor_sync(0xffffffffu, s1, o);
        s2 += __shfl_xor_sync(0xffffffffu, s2, o);
    }
    if (lane == 0) { g_zn1[n] = s1; g_zn2[n] = s2; }
}

__global__ void k_scatter2(const int* __restrict__ eid, const int* __restrict__ dst) {
    __shared__ int h[R_], base[R_], cur[R_];
    int tid = threadIdx.x;
    if (tid < R_) { h[tid] = 0; cur[tid] = 0; }
    __syncthreads();
    int e = blockIdx.x * blockDim.x + tid;
    int r = (e < E_) ? eid[e] : -1;
    if (r >= 0) atomicAdd(&h[r], 1);
    __syncthreads();
    if (tid < R_ && h[tid] > 0) base[tid] = atomicAdd(&g_cur[tid], h[tid]);
    __syncthreads();
    if (r >= 0) {
        int p = base[r] + atomicAdd(&cur[r], 1);
        g_perm[p] = e;
        g_epos[e] = atomicAdd(&g_dcur[dst[e]], 1);
    }
}

// ---- dense self-loop GEMM: sl = ne @ L   (128 nodes x NOUT, K=64) ----
template <int NOUT>
__global__ void __launch_bounds__(256, 2)
k_selfgemm(const float* __restrict__ ne, const float* __restrict__ Lf,
           float* __restrict__ sl) {
    constexpr int AST = 36;
    constexpr int AW  = BM * AST;
    constexpr int BWF = NOUT * 32;
    constexpr int NF  = NOUT / 16;
    constexpr int NFH = NF / 2;

    extern __shared__ __align__(16) float dyn[];
    float* Asm = dyn;

    const int tid = threadIdx.x;
    const int n0  = blockIdx.x * BM;
    const uint32_t a_s0 = smem_u32(Asm);

#pragma unroll
    for (int c = 0; c < 2; c++) {
#pragma unroll
        for (int t = 0; t < 4; t++) {
            int i = tid + t * 256;
            int row = i >> 3, u = i & 7;
            int n = n0 + row;
            const float* src = ne + (size_t)(n < N_ ? n : N_ - 1) * 64 + c * 32 + u * 4;
            cp_async16(a_s0 + (c * AW + row * AST) * 4 + u * 16, src);
        }
    }
    asm volatile("cp.async.commit_group;" ::: "memory");
    asm volatile("cp.async.wait_group 0;" ::: "memory");
    __syncthreads();

    const int warp = tid >> 5, lane = tid & 31;
    const int wr = warp & 3, wc = warp >> 2;
    const int g = lane >> 2, q = lane & 3;

    float acc[2][NF][4];
#pragma unroll
    for (int mg = 0; mg < 2; mg++)
#pragma unroll
        for (int nf = 0; nf < NF; nf++)
#pragma unroll
            for (int j = 0; j < 4; j++) acc[mg][nf][j] = 0.f;

#pragma unroll
    for (int c = 0; c < 2; c++) {
        const float* ab = Asm + c * AW;
        const float* bb = Lf + (size_t)c * BWF;
#pragma unroll
        for (int ks = 0; ks < 4; ks++) {
            uint32_t a[2][4];
#pragma unroll
            for (int mg = 0; mg < 2; mg++) {
                const float* ap = ab + (wr * 32 + mg * 16 + g) * AST + ks * 8 + q;
                a[mg][0] = __float_as_uint(ap[0]);
                a[mg][1] = __float_as_uint(ap[8 * AST]);
                a[mg][2] = __float_as_uint(ap[4]);
                a[mg][3] = __float_as_uint(ap[8 * AST + 4]);
            }
#pragma unroll
            for (int j = 0; j < NFH; j++) {
                float4 bv = __ldg((const float4*)(bb +
                    (((ks * 2 + wc) * NFH + j) * 32 + lane) * 4));
                uint32_t b0a = __float_as_uint(bv.x), b1a = __float_as_uint(bv.y);
                uint32_t b0b = __float_as_uint(bv.z), b1b = __float_as_uint(bv.w);
#pragma unroll
                for (int mg = 0; mg < 2; mg++) {
                    asm volatile(
                        "mma.sync.aligned.m16n8k8.row.col.f32.tf32.tf32.f32 "
                        "{%0,%1,%2,%3},{%4,%5,%6,%7},{%8,%9},{%0,%1,%2,%3};"
                        : "+f"(acc[mg][2 * j][0]), "+f"(acc[mg][2 * j][1]),
                          "+f"(acc[mg][2 * j][2]), "+f"(acc[mg][2 * j][3])
                        : "r"(a[mg][0]), "r"(a[mg][1]), "r"(a[mg][2]), "r"(a[mg][3]),
                          "r"(b0a), "r"(b1a));
                    asm volatile(
                        "mma.sync.aligned.m16n8k8.row.col.f32.tf32.tf32.f32 "
                        "{%0,%1,%2,%3},{%4,%5,%6,%7},{%8,%9},{%0,%1,%2,%3};"
                        : "+f"(acc[mg][2 * j + 1][0]), "+f"(acc[mg][2 * j + 1][1]),
                          "+f"(acc[mg][2 * j + 1][2]), "+f"(acc[mg][2 * j + 1][3])
                        : "r"(a[mg][0]), "r"(a[mg][1]), "r"(a[mg][2]), "r"(a[mg][3]),
                          "r"(b0b), "r"(b1b));
                }
            }
        }
    }

#pragma unroll
    for (int mg = 0; mg < 2; mg++) {
        int r0 = wr * 32 + mg * 16 + g;
        int na = n0 + r0, nb = na + 8;
#pragma unroll
        for (int nf = 0; nf < NF; nf++) {
            int col = wc * (NOUT / 2) + nf * 8 + 2 * q;
            if (na < N_)
                *(float2*)(sl + (size_t)na * NOUT + col) =
                    make_float2(acc[mg][nf][0], acc[mg][nf][1]);
            if (nb < N_)
                *(float2*)(sl + (size_t)nb * NOUT + col) =
                    make_float2(acc[mg][nf][2], acc[mg][nf][3]);
        }
    }
}

// ---- 4-stage A-pipeline tf32 mma grouped gather-GEMM; B via __ldg ----------
template <int FIN, int NOUT>
__global__ void __launch_bounds__(256, 2)
k_gemm_mma(const float* __restrict__ Wt, const float* __restrict__ At,
           const float* __restrict__ zn,
           const int* __restrict__ src, const int* __restrict__ dst,
           const float* __restrict__ ef, const float* __restrict__ ne) {
    constexpr int K    = FIN + 2 * EMB_;
    constexpr int NC   = K / 32;
    constexpr int AST  = 36;
    constexpr int AW   = BM * AST;
    constexpr int BWF  = NOUT * 32;
    constexpr int NF   = NOUT / 16;
    constexpr int NFH  = NF / 2;

    extern __shared__ __align__(16) float dyn[];
    float* Asm = dyn;                            // 4 buffers
    __shared__ const float* s_p[3][BM];
    __shared__ int   s_pos[BM];
    __shared__ int   s_dst[BM];
    __shared__ float s_At[NOUT];
    __shared__ float s_zr[BM];

    const int tid = threadIdx.x;
    const int m0  = blockIdx.x * BM;
    if (m0 >= g_off[R_]) return;

    int rel = 0;
#pragma unroll
    for (int r = 1; r < R_; r++)
        if (m0 >= g_off[r]) rel = r;
    const int seg_end = g_off[rel] + g_cnt[rel];

    if (tid < BM) {
        int gi = m0 + tid;
        int e = (gi < seg_end) ? g_perm[gi] : -1;
        if (e >= 0) {
            s_pos[tid]  = g_epos[e];
            s_p[0][tid] = g_hn + (size_t)src[e] * FIN;
            s_p[1][tid] = ef + (size_t)e * EMB_;
            s_p[2][tid] = ne + (size_t)dst[e] * EMB_;
            s_dst[tid]  = dst[e];
        } else {
            s_pos[tid] = -1;
            s_p[0][tid] = g_hn; s_p[1][tid] = g_hn; s_p[2][tid] = g_hn;
            s_dst[tid] = 0;
        }
    }
    if (tid < NOUT) s_At[tid] = At[tid];
    __syncthreads();

    const float* wblob = Wt + (size_t)rel * NC * BWF;
    const uint32_t a_s0 = smem_u32(Asm);

    auto load_chunk = [&](int c, int buf) {
        const int k0 = c * 32;
        int seg, off;
        if (k0 < FIN)              { seg = 0; off = k0; }
        else if (k0 < FIN + EMB_)  { seg = 1; off = k0 - FIN; }
        else                       { seg = 2; off = k0 - FIN - EMB_; }
        const uint32_t ab = a_s0 + buf * AW * 4;
#pragma unroll
        for (int t = 0; t < 4; t++) {
            int i = tid + t * 256;
            int row = i >> 3, u = i & 7;
            cp_async16(ab + (row * AST) * 4 + u * 16, s_p[seg][row] + off + u * 4);
        }
        asm volatile("cp.async.commit_group;" ::: "memory");
    };

    const int warp = tid >> 5, lane = tid & 31;
    const int wr = warp & 3, wc = warp >> 2;
    const int g = lane >> 2, q = lane & 3;

    float acc[2][NF][4];
#pragma unroll
    for (int mg = 0; mg < 2; mg++)
#pragma unroll
        for (int nf = 0; nf < NF; nf++)
#pragma unroll
            for (int j = 0; j < 4; j++) acc[mg][nf][j] = 0.f;

    load_chunk(0, 0);
    load_chunk(1, 1);
    load_chunk(2, 2);

    for (int c = 0; c < NC; c++) {
        asm volatile("cp.async.wait_group 2;" ::: "memory");
        __syncthreads();
        if (c + 3 < NC) load_chunk(c + 3, (c + 3) & 3);
        else asm volatile("cp.async.commit_group;" ::: "memory");

        const float* ab = Asm + (c & 3) * AW;
        const float* bb = wblob + (size_t)c * BWF;
#pragma unroll
        for (int ks = 0; ks < 4; ks++) {
            uint32_t a[2][4];
#pragma unroll
            for (int mg = 0; mg < 2; mg++) {
                const float* ap = ab + (wr * 32 + mg * 16 + g) * AST + ks * 8 + q;
                a[mg][0] = __float_as_uint(ap[0]);
                a[mg][1] = __float_as_uint(ap[8 * AST]);
                a[mg][2] = __float_as_uint(ap[4]);
                a[mg][3] = __float_as_uint(ap[8 * AST + 4]);
            }
#pragma unroll
            for (int j = 0; j < NFH; j++) {
                float4 bv = __ldg((const float4*)(bb +
                    (((ks * 2 + wc) * NFH + j) * 32 + lane) * 4));
                uint32_t b0a = __float_as_uint(bv.x), b1a = __float_as_uint(bv.y);
                uint32_t b0b = __float_as_uint(bv.z), b1b = __float_as_uint(bv.w);
#pragma unroll
                for (int mg = 0; mg < 2; mg++) {
                    asm volatile(
                        "mma.sync.aligned.m16n8k8.row.col.f32.tf32.tf32.f32 "
                        "{%0,%1,%2,%3},{%4,%5,%6,%7},{%8,%9},{%0,%1,%2,%3};"
                        : "+f"(acc[mg][2 * j][0]), "+f"(acc[mg][2 * j][1]),
                          "+f"(acc[mg][2 * j][2]), "+f"(acc[mg][2 * j][3])
                        : "r"(a[mg][0]), "r"(a[mg][1]), "r"(a[mg][2]), "r"(a[mg][3]),
                          "r"(b0a), "r"(b1a));
                    asm volatile(
                        "mma.sync.aligned.m16n8k8.row.col.f32.tf32.tf32.f32 "
                        "{%0,%1,%2,%3},{%4,%5,%6,%7},{%8,%9},{%0,%1,%2,%3};"
                        : "+f"(acc[mg][2 * j + 1][0]), "+f"(acc[mg][2 * j + 1][1]),
                          "+f"(acc[mg][2 * j + 1][2]), "+f"(acc[mg][2 * j + 1][3])
                        : "r"(a[mg][0]), "r"(a[mg][1]), "r"(a[mg][2]), "r"(a[mg][3]),
                          "r"(b0b), "r"(b1b));
                }
            }
        }
    }
    __syncthreads();

    // ---- store m rows (streaming, dst-CSR) + fused attention logits ----
    float p0[2], p1[2];
#pragma unroll
    for (int mg = 0; mg < 2; mg++) {
        int r0 = wr * 32 + mg * 16 + g;
        int d0 = s_pos[r0], d1 = s_pos[r0 + 8];
        p0[mg] = 0.f; p1[mg] = 0.f;
#pragma unroll
        for (int nf = 0; nf < NF; nf++) {
            int col = wc * (NOUT / 2) + nf * 8 + 2 * q;
            float a0 = s_At[col], a1 = s_At[col + 1];
            p0[mg] += acc[mg][nf][0] * a0 + acc[mg][nf][1] * a1;
            p1[mg] += acc[mg][nf][2] * a0 + acc[mg][nf][3] * a1;
            if (d0 >= 0)
                st_cs_f2(g_m + (size_t)d0 * NOUT + col,
                         acc[mg][nf][0], acc[mg][nf][1]);
            if (d1 >= 0)
                st_cs_f2(g_m + (size_t)d1 * NOUT + col,
                         acc[mg][nf][2], acc[mg][nf][3]);
        }
        p0[mg] += __shfl_xor_sync(0xffffffffu, p0[mg], 1);
        p0[mg] += __shfl_xor_sync(0xffffffffu, p0[mg], 2);
        p1[mg] += __shfl_xor_sync(0xffffffffu, p1[mg], 1);
        p1[mg] += __shfl_xor_sync(0xffffffffu, p1[mg], 2);
    }
    if (wc == 0 && q == 0) {
#pragma unroll
        for (int mg = 0; mg < 2; mg++) {
            s_zr[wr * 32 + mg * 16 + g]     = p0[mg];
            s_zr[wr * 32 + mg * 16 + g + 8] = p1[mg];
        }
    }
    __syncthreads();
    if (wc == 1 && q == 0) {
#pragma unroll
        for (int mg = 0; mg < 2; mg++) {
#pragma unroll
            for (int h = 0; h < 2; h++) {
                int r = wr * 32 + mg * 16 + g + h * 8;
                int p = s_pos[r];
                if (p >= 0) {
                    float tot = s_zr[r] + (h == 0 ? p0[mg] : p1[mg]);
                    float z = zn[s_dst[r]] + tot;
                    z = (z > 0.f) ? z : 0.01f * z;
                    g_z[p] = z;
                }
            }
        }
    }
}

// ------ fused: segment softmax + streaming aggregation + final epilogue ----
template <int NOUT, bool OUT_HN>
__global__ void __launch_bounds__(256)
k_aggfinal(const float* __restrict__ sl, const float* __restrict__ b,
           float* __restrict__ out) {
    const int tid = threadIdx.x;
    const int warp = tid >> 5, lane = tid & 31;
#pragma unroll
    for (int it = 0; it < 4; it++) {
        int n = blockIdx.x * 32 + it * 8 + warp;
        if (n >= N_) continue;
        int beg = g_doff[n], cnt = g_indeg_i[n];

        float zm = -3.4e38f;
        for (int i = lane; i < cnt; i += 32) zm = fmaxf(zm, g_z[beg + i]);
#pragma unroll
        for (int o = 16; o; o >>= 1)
            zm = fmaxf(zm, __shfl_xor_sync(0xffffffffu, zm, o));

        float iv = g_inv_in[n];

        if (NOUT == 128) {
            float4 acc = make_float4(0.f, 0.f, 0.f, 0.f);
            float den = 0.f;
            const float* mrow = g_m + (size_t)beg * 128 + lane * 4;
            for (int i = 0; i < cnt; i++) {
                float w = __expf(g_z[beg + i] - zm);
                den += w;
                float4 v = ld_cs_f4(mrow + (size_t)i * 128);
                acc.x += w * v.x; acc.y += w * v.y;
                acc.z += w * v.z; acc.w += w * v.w;
            }
            float invw = (cnt > 0) ? 1.f / den : 0.f;
            float4 lt = *(const float4*)(sl + (size_t)n * 128 + lane * 4);
            float4 bb = *(const float4*)(b + lane * 4);
            float4 r;
            r.x = fmaxf((acc.x * invw + lt.x) * iv + bb.x, 0.f);
            r.y = fmaxf((acc.y * invw + lt.y) * iv + bb.y, 0.f);
            r.z = fmaxf((acc.z * invw + lt.z) * iv + bb.z, 0.f);
            r.w = fmaxf((acc.w * invw + lt.w) * iv + bb.w, 0.f);
            if (OUT_HN) {
                float so = g_inv_out[n];
                *(float4*)(g_hn + (size_t)n * 128 + lane * 4) =
                    make_float4(r.x * so, r.y * so, r.z * so, r.w * so);
            } else {
                *(float4*)(out + (size_t)n * 128 + lane * 4) = r;
            }
        } else {
            float2 acc = make_float2(0.f, 0.f);
            float den = 0.f;
            const float* mrow = g_m + (size_t)beg * 64 + lane * 2;
            for (int i = 0; i < cnt; i++) {
                float w = __expf(g_z[beg + i] - zm);
                den += w;
                float2 v = ld_cs_f2(mrow + (size_t)i * 64);
                acc.x += w * v.x; acc.y += w * v.y;
            }
            float invw = (cnt > 0) ? 1.f / den : 0.f;
            float2 lt = *(const float2*)(sl + (size_t)n * 64 + lane * 2);
            float2 bb = *(const float2*)(b + lane * 2);
            float2 r;
            r.x = fmaxf((acc.x * invw + lt.x) * iv + bb.x, 0.f);
            r.y = fmaxf((acc.y * invw + lt.y) * iv + bb.y, 0.f);
            *(float2*)(out + (size_t)n * 64 + lane * 2) = r;
        }
    }
}

// ------------------------------- launcher ----------------------------------
extern "C" void kernel_launch(void* const* d_in, const int* in_sizes, int n_in,
                              void* d_out, int out_size) {
    const float* node_emb  = (const float*)d_in[0];
    const float* edge_feat = (const float*)d_in[1];
    const float* W1        = (const float*)d_in[2];
    const float* A1        = (const float*)d_in[3];
    const float* b1        = (const float*)d_in[4];
    const float* L1        = (const float*)d_in[5];
    const float* W2        = (const float*)d_in[6];
    const float* A2        = (const float*)d_in[7];
    const float* b2        = (const float*)d_in[8];
    const float* L2        = (const float*)d_in[9];
    const int*   eid       = (const int*)d_in[10];
    const int*   src       = (const int*)d_in[11];
    const int*   dst       = (const int*)d_in[12];
    float*       out       = (float*)d_out;
    (void)in_sizes; (void)n_in; (void)out_size;

    const int gE = (E_ + 255) / 256;
    const int NT = (N_ + BM - 1) / BM;

    float* d_Wt1; cudaGetSymbolAddress((void**)&d_Wt1, g_Wt1);
    float* d_Wt2; cudaGetSymbolAddress((void**)&d_Wt2, g_Wt2);
    float* d_Lf1; cudaGetSymbolAddress((void**)&d_Lf1, g_Lf1);
    float* d_Lf2; cudaGetSymbolAddress((void**)&d_Lf2, g_Lf2);
    float* d_sl1; cudaGetSymbolAddress((void**)&d_sl1, g_sl1);
    float* d_sl2; cudaGetSymbolAddress((void**)&d_sl2, g_sl2);
    float* d_zn1; cudaGetSymbolAddress((void**)&d_zn1, g_zn1);
    float* d_zn2; cudaGetSymbolAddress((void**)&d_zn2, g_zn2);

    const int DSA = 4 * BM * 36 * 4;                     // 73728 (A-only, both)
    const int SGA = 2 * BM * 36 * 4;                     // 36864
    cudaFuncSetAttribute(k_gemm_mma<64, 128>,
                         cudaFuncAttributeMaxDynamicSharedMemorySize, DSA);
    cudaFuncSetAttribute(k_gemm_mma<128, 64>,
                         cudaFuncAttributeMaxDynamicSharedMemorySize, DSA);
    cudaFuncSetAttribute(k_selfgemm<128>,
                         cudaFuncAttributeMaxDynamicSharedMemorySize, SGA);
    cudaFuncSetAttribute(k_selfgemm<64>,
                         cudaFuncAttributeMaxDynamicSharedMemorySize, SGA);

    // ---- prep ----
    k_zero_wfrag<<<(WT1 + WT2 + SL1F + SL2F + 255) / 256, 256>>>(W1, W2, L1, L2);
    k_selfgemm<128><<<NT, 256, SGA>>>(node_emb, d_Lf1, d_sl1);
    k_selfgemm<64><<<NT, 256, SGA>>>(node_emb, d_Lf2, d_sl2);
    k_count<<<gE, 256>>>(src, dst, eid);
    k_scan_blk<<<SCAN_NB, SCAN_BS>>>();
    k_scan_top<<<1, 64>>>();
    k_scan_addnode<<<(N_ + 7) / 8, 256>>>(node_emb, A1, A2);
    k_scatter2<<<gE, 256>>>(eid, dst);

    // ---- layer 1: FIN=64, K=192, NOUT=128 ----
    k_gemm_mma<64, 128><<<MT, 256, DSA>>>(d_Wt1, A1 + EMB_, d_zn1, src, dst,
                                          edge_feat, node_emb);
    k_aggfinal<128, true><<<(N_ + 31) / 32, 256>>>(d_sl1, b1, nullptr);

    // ---- layer 2: FIN=128, K=256, NOUT=64 ----
    k_gemm_mma<128, 64><<<MT, 256, DSA>>>(d_Wt2, A2 + EMB_, d_zn2, src, dst,
                                          edge_feat, node_emb);
    k_aggfinal<64, false><<<(N_ + 31) / 32, 256>>>(d_sl2, b2, out);
}

// round 17
// speedup vs baseline: 1.0947x; 1.0947x over previous
#include <cuda_runtime.h>
#include <math.h>
#include <stdint.h>

// ---------------------------------------------------------------------------
// RelationalPathGNN — round 17
//   * revert to round-15 champion GEMM (3-stage A+B cp.async pipeline;
//     B-via-__ldg was the round-16 regression: exposed L2 latency in the
//     MMA inner loop)
//   * k_aggfinal: 2-way unrolled accumulation (independent acc pairs, 2x MLP)
// ---------------------------------------------------------------------------

namespace {
constexpr int N_   = 20000;
constexpr int E_   = 160000;
constexpr int EMB_ = 64;
constexpr int HID_ = 128;
constexpr int R_   = 8;
constexpr int BM   = 128;                       // rows per GEMM tile
constexpr int MT   = E_ / BM + R_;              // 1258 worst-case tiles
constexpr int SCAN_BS = 512;
constexpr int SCAN_NB = (N_ + SCAN_BS - 1) / SCAN_BS;   // 40
constexpr int WT1 = R_ * 6 * HID_ * 32;         // W1 frag floats (196608)
constexpr int WT2 = R_ * 8 * EMB_ * 32;         // W2 frag floats (131072)
constexpr int SL1F = 2 * HID_ * 32;             // L1 frag floats (8192)
constexpr int SL2F = 2 * EMB_ * 32;             // L2 frag floats (4096)
}

// ------------------------- scratch (static device) -------------------------
__device__ float    g_m[(size_t)E_ * HID_];     // edge messages (fp32, dst-CSR)
__device__ float    g_z[E_];                    // logits, dst-CSR order
__device__ float    g_hn[(size_t)N_ * HID_];    // degree-scaled h
__device__ float    g_Wt1[WT1];                 // W1 fragment-major, rna tf32
__device__ float    g_Wt2[WT2];                 // W2 fragment-major, rna tf32
__device__ float    g_Lf1[SL1F];                // L1 fragment-major, rna tf32
__device__ float    g_Lf2[SL2F];                // L2 fragment-major, rna tf32
__device__ float    g_sl1[(size_t)N_ * HID_];   // self-loop ne@L1
__device__ float    g_sl2[(size_t)N_ * EMB_];   // self-loop ne@L2
__device__ float    g_inv_out[N_], g_inv_in[N_];
__device__ int      g_outdeg_i[N_], g_indeg_i[N_];
__device__ int      g_cnt[R_], g_off[R_ + 1], g_cur[R_];
__device__ int      g_perm[E_ + R_ * BM];
__device__ int      g_doff[N_], g_dcur[N_], g_dtmp[N_], g_dblk[SCAN_NB];
__device__ int      g_epos[E_];                 // edge -> dst-CSR position
__device__ float    g_zn1[N_], g_zn2[N_];

// ------------------------------ helpers ------------------------------------
__device__ __forceinline__ uint32_t tf32r(float x) {
    uint32_t u;
    asm("cvt.rna.tf32.f32 %0, %1;" : "=r"(u) : "f"(x));
    return u;
}
__device__ __forceinline__ uint32_t smem_u32(const void* p) {
    uint32_t a;
    asm("{ .reg .u64 t; cvta.to.shared.u64 t, %1; cvt.u32.u64 %0, t; }"
        : "=r"(a) : "l"(p));
    return a;
}
__device__ __forceinline__ void cp_async16(uint32_t daddr, const void* gptr) {
    asm volatile("cp.async.cg.shared.global [%0], [%1], 16;"
                 :: "r"(daddr), "l"(gptr) : "memory");
}
__device__ __forceinline__ void st_cs_f2(float* p, float a, float b) {
    asm volatile("st.global.cs.v2.f32 [%0], {%1, %2};"
                 :: "l"(p), "f"(a), "f"(b) : "memory");
}
__device__ __forceinline__ float4 ld_cs_f4(const float* p) {
    float4 v;
    asm volatile("ld.global.cs.v4.f32 {%0, %1, %2, %3}, [%4];"
                 : "=f"(v.x), "=f"(v.y), "=f"(v.z), "=f"(v.w) : "l"(p));
    return v;
}
__device__ __forceinline__ float2 ld_cs_f2(const float* p) {
    float2 v;
    asm volatile("ld.global.cs.v2.f32 {%0, %1}, [%2];"
                 : "=f"(v.x), "=f"(v.y) : "l"(p));
    return v;
}

// ---- weight bake helper (fragment-major, rna tf32) ----
template <int K, int NOUT>
__device__ __forceinline__ void wfrag_one(const float* __restrict__ W,
                                          float* __restrict__ out, int idx) {
    constexpr int KC = K / 32;
    constexpr int NFH = NOUT / 32;
    int i  = idx % (NOUT * 32);
    int rc = idx / (NOUT * 32);
    int c  = rc % KC, r = rc / KC;
    int f    = i & 3;
    int t    = i >> 2;
    int lane = t & 31;
    int t2   = t >> 5;
    int j    = t2 % NFH;
    int t3   = t2 / NFH;
    int wc   = t3 & 1;
    int ks   = t3 >> 1;
    int g = lane >> 2, q = lane & 3;
    int k   = c * 32 + ks * 8 + q + (f & 1) * 4;
    int col = wc * (NOUT / 2) + (2 * j + (f >> 1)) * 8 + g;
    out[idx] = __uint_as_float(tf32r(W[((size_t)r * K + k) * NOUT + col]));
}

// ------------------------------ prep kernels -------------------------------
__global__ void k_zero_wfrag(const float* __restrict__ W1,
                             const float* __restrict__ W2,
                             const float* __restrict__ L1,
                             const float* __restrict__ L2) {
    int i = blockIdx.x * blockDim.x + threadIdx.x;
    if (i < N_) { g_outdeg_i[i] = 0; g_indeg_i[i] = 0; }
    if (i < R_) g_cnt[i] = 0;
    if (i < WT1)                          wfrag_one<192, 128>(W1, g_Wt1, i);
    else if (i < WT1 + WT2)               wfrag_one<256, 64>(W2, g_Wt2, i - WT1);
    else if (i < WT1 + WT2 + SL1F)        wfrag_one<64, 128>(L1, g_Lf1, i - WT1 - WT2);
    else if (i < WT1 + WT2 + SL1F + SL2F) wfrag_one<64, 64>(L2, g_Lf2, i - WT1 - WT2 - SL1F);
}

__global__ void k_count(const int* __restrict__ src, const int* __restrict__ dst,
                        const int* __restrict__ eid) {
    __shared__ int h[R_];
    int tid = threadIdx.x;
    if (tid < R_) h[tid] = 0;
    __syncthreads();
    int e = blockIdx.x * blockDim.x + tid;
    if (e < E_) {
        atomicAdd(&g_outdeg_i[src[e]], 1);
        atomicAdd(&g_indeg_i[dst[e]], 1);
        atomicAdd(&h[eid[e]], 1);
    }
    __syncthreads();
    if (tid < R_ && h[tid] > 0) atomicAdd(&g_cnt[tid], h[tid]);
}

// ---- parallel dst-CSR scan chain (40 blocks) ----
__global__ void k_scan_blk() {
    __shared__ int sh[SCAN_BS];
    int i = blockIdx.x * SCAN_BS + threadIdx.x;
    int v = (i < N_) ? g_indeg_i[i] : 0;
    sh[threadIdx.x] = v;
    __syncthreads();
    for (int o = 1; o < SCAN_BS; o <<= 1) {
        int t = (threadIdx.x >= o) ? sh[threadIdx.x - o] : 0;
        __syncthreads();
        sh[threadIdx.x] += t;
        __syncthreads();
    }
    if (i < N_) g_dtmp[i] = sh[threadIdx.x] - v;
    if (threadIdx.x == SCAN_BS - 1) g_dblk[blockIdx.x] = sh[SCAN_BS - 1];
}

__global__ void k_scan_top() {
    if (threadIdx.x == 0) {
        int o = 0;
        for (int r = 0; r < R_; r++) {
            g_off[r] = o; g_cur[r] = o;
            o += ((g_cnt[r] + BM - 1) / BM) * BM;
        }
        g_off[R_] = o;
    } else if (threadIdx.x == 32) {
        int a = 0;
        for (int b = 0; b < SCAN_NB; b++) { int t = g_dblk[b]; g_dblk[b] = a; a += t; }
    }
}

// merged (warp-per-node): finish dst scan + normalizers + hn + zn1/zn2 dots
__global__ void k_scan_addnode(const float* __restrict__ ne,
                               const float* __restrict__ A1,
                               const float* __restrict__ A2) {
    int gt = blockIdx.x * blockDim.x + threadIdx.x;
    int n = gt >> 5, lane = gt & 31;
    if (n >= N_) return;
    float so, si;
    if (lane == 0) {
        int o = g_dtmp[n] + g_dblk[n / SCAN_BS];
        g_doff[n] = o; g_dcur[n] = o;
        so = 1.f / sqrtf(fmaxf((float)g_outdeg_i[n], 1.f));
        si = 1.f / sqrtf(fmaxf((float)g_indeg_i[n], 1.f));
        g_inv_out[n] = so; g_inv_in[n] = si;
    }
    so = __shfl_sync(0xffffffffu, so, 0);
    float x0 = ne[(size_t)n * 64 + lane], x1 = ne[(size_t)n * 64 + 32 + lane];
    g_hn[(size_t)n * 64 + lane]      = x0 * so;
    g_hn[(size_t)n * 64 + 32 + lane] = x1 * so;
    float s1 = x0 * A1[lane] + x1 * A1[32 + lane];
    float s2 = x0 * A2[lane] + x1 * A2[32 + lane];
#pragma unroll
    for (int o = 16; o; o >>= 1) {
        s1 += __shfl_xor_sync(0xffffffffu, s1, o);
        s2 += __shfl_xor_sync(0xffffffffu, s2, o);
    }
    if (lane == 0) { g_zn1[n] = s1; g_zn2[n] = s2; }
}

__global__ void k_scatter2(const int* __restrict__ eid, const int* __restrict__ dst) {
    __shared__ int h[R_], base[R_], cur[R_];
    int tid = threadIdx.x;
    if (tid < R_) { h[tid] = 0; cur[tid] = 0; }
    __syncthreads();
    int e = blockIdx.x * blockDim.x + tid;
    int r = (e < E_) ? eid[e] : -1;
    if (r >= 0) atomicAdd(&h[r], 1);
    __syncthreads();
    if (tid < R_ && h[tid] > 0) base[tid] = atomicAdd(&g_cur[tid], h[tid]);
    __syncthreads();
    if (r >= 0) {
        int p = base[r] + atomicAdd(&cur[r], 1);
        g_perm[p] = e;
        g_epos[e] = atomicAdd(&g_dcur[dst[e]], 1);
    }
}

// ---- dense self-loop GEMM: sl = ne @ L   (128 nodes x NOUT, K=64) ----
template <int NOUT>
__global__ void __launch_bounds__(256, 2)
k_selfgemm(const float* __restrict__ ne, const float* __restrict__ Lf,
           float* __restrict__ sl) {
    constexpr int AST = 36;
    constexpr int AW  = BM * AST;
    constexpr int BWF = NOUT * 32;
    constexpr int NF  = NOUT / 16;
    constexpr int NFH = NF / 2;

    extern __shared__ __align__(16) float dyn[];
    float* Asm = dyn;
    float* Bsm = dyn + 2 * AW;

    const int tid = threadIdx.x;
    const int n0  = blockIdx.x * BM;
    const uint32_t a_s0 = smem_u32(Asm);
    const uint32_t b_s0 = smem_u32(Bsm);

#pragma unroll
    for (int c = 0; c < 2; c++) {
#pragma unroll
        for (int t = 0; t < 4; t++) {
            int i = tid + t * 256;
            int row = i >> 3, u = i & 7;
            int n = n0 + row;
            const float* src = ne + (size_t)(n < N_ ? n : N_ - 1) * 64 + c * 32 + u * 4;
            cp_async16(a_s0 + (c * AW + row * AST) * 4 + u * 16, src);
        }
        const float* wb = Lf + (size_t)c * BWF;
        const uint32_t bb = b_s0 + c * BWF * 4;
        for (int i = tid * 4; i < BWF; i += 256 * 4)
            cp_async16(bb + i * 4, wb + i);
    }
    asm volatile("cp.async.commit_group;" ::: "memory");
    asm volatile("cp.async.wait_group 0;" ::: "memory");
    __syncthreads();

    const int warp = tid >> 5, lane = tid & 31;
    const int wr = warp & 3, wc = warp >> 2;
    const int g = lane >> 2, q = lane & 3;

    float acc[2][NF][4];
#pragma unroll
    for (int mg = 0; mg < 2; mg++)
#pragma unroll
        for (int nf = 0; nf < NF; nf++)
#pragma unroll
            for (int j = 0; j < 4; j++) acc[mg][nf][j] = 0.f;

#pragma unroll
    for (int c = 0; c < 2; c++) {
        const float* ab = Asm + c * AW;
        const float* bb = Bsm + c * BWF;
#pragma unroll
        for (int ks = 0; ks < 4; ks++) {
            uint32_t a[2][4];
#pragma unroll
            for (int mg = 0; mg < 2; mg++) {
                const float* ap = ab + (wr * 32 + mg * 16 + g) * AST + ks * 8 + q;
                a[mg][0] = __float_as_uint(ap[0]);
                a[mg][1] = __float_as_uint(ap[8 * AST]);
                a[mg][2] = __float_as_uint(ap[4]);
                a[mg][3] = __float_as_uint(ap[8 * AST + 4]);
            }
#pragma unroll
            for (int j = 0; j < NFH; j++) {
                float4 bv = *(const float4*)(bb +
                    (((ks * 2 + wc) * NFH + j) * 32 + lane) * 4);
                uint32_t b0a = __float_as_uint(bv.x), b1a = __float_as_uint(bv.y);
                uint32_t b0b = __float_as_uint(bv.z), b1b = __float_as_uint(bv.w);
#pragma unroll
                for (int mg = 0; mg < 2; mg++) {
                    asm volatile(
                        "mma.sync.aligned.m16n8k8.row.col.f32.tf32.tf32.f32 "
                        "{%0,%1,%2,%3},{%4,%5,%6,%7},{%8,%9},{%0,%1,%2,%3};"
                        : "+f"(acc[mg][2 * j][0]), "+f"(acc[mg][2 * j][1]),
                          "+f"(acc[mg][2 * j][2]), "+f"(acc[mg][2 * j][3])
                        : "r"(a[mg][0]), "r"(a[mg][1]), "r"(a[mg][2]), "r"(a[mg][3]),
                          "r"(b0a), "r"(b1a));
                    asm volatile(
                        "mma.sync.aligned.m16n8k8.row.col.f32.tf32.tf32.f32 "
                        "{%0,%1,%2,%3},{%4,%5,%6,%7},{%8,%9},{%0,%1,%2,%3};"
                        : "+f"(acc[mg][2 * j + 1][0]), "+f"(acc[mg][2 * j + 1][1]),
                          "+f"(acc[mg][2 * j + 1][2]), "+f"(acc[mg][2 * j + 1][3])
                        : "r"(a[mg][0]), "r"(a[mg][1]), "r"(a[mg][2]), "r"(a[mg][3]),
                          "r"(b0b), "r"(b1b));
                }
            }
        }
    }

#pragma unroll
    for (int mg = 0; mg < 2; mg++) {
        int r0 = wr * 32 + mg * 16 + g;
        int na = n0 + r0, nb = na + 8;
#pragma unroll
        for (int nf = 0; nf < NF; nf++) {
            int col = wc * (NOUT / 2) + nf * 8 + 2 * q;
            if (na < N_)
                *(float2*)(sl + (size_t)na * NOUT + col) =
                    make_float2(acc[mg][nf][0], acc[mg][nf][1]);
            if (nb < N_)
                *(float2*)(sl + (size_t)nb * NOUT + col) =
                    make_float2(acc[mg][nf][2], acc[mg][nf][3]);
        }
    }
}

// --------- 3-stage pipelined tf32 mma grouped gather-GEMM ------------------
template <int FIN, int NOUT>
__global__ void __launch_bounds__(256, 2)
k_gemm_mma(const float* __restrict__ Wt, const float* __restrict__ At,
           const float* __restrict__ zn,
           const int* __restrict__ src, const int* __restrict__ dst,
           const float* __restrict__ ef, const float* __restrict__ ne) {
    constexpr int K    = FIN + 2 * EMB_;
    constexpr int NC   = K / 32;
    constexpr int AST  = 36;
    constexpr int AW   = BM * AST;
    constexpr int BWF  = NOUT * 32;
    constexpr int NF   = NOUT / 16;
    constexpr int NFH  = NF / 2;

    extern __shared__ __align__(16) float dyn[];
    float* Asm = dyn;
    float* Bsm = dyn + 3 * AW;
    __shared__ const float* s_p[3][BM];
    __shared__ int   s_pos[BM];
    __shared__ int   s_dst[BM];
    __shared__ float s_At[NOUT];
    __shared__ float s_zr[BM];

    const int tid = threadIdx.x;
    const int m0  = blockIdx.x * BM;
    if (m0 >= g_off[R_]) return;

    int rel = 0;
#pragma unroll
    for (int r = 1; r < R_; r++)
        if (m0 >= g_off[r]) rel = r;
    const int seg_end = g_off[rel] + g_cnt[rel];

    if (tid < BM) {
        int gi = m0 + tid;
        int e = (gi < seg_end) ? g_perm[gi] : -1;
        if (e >= 0) {
            s_pos[tid]  = g_epos[e];
            s_p[0][tid] = g_hn + (size_t)src[e] * FIN;
            s_p[1][tid] = ef + (size_t)e * EMB_;
            s_p[2][tid] = ne + (size_t)dst[e] * EMB_;
            s_dst[tid]  = dst[e];
        } else {
            s_pos[tid] = -1;
            s_p[0][tid] = g_hn; s_p[1][tid] = g_hn; s_p[2][tid] = g_hn;
            s_dst[tid] = 0;
        }
    }
    if (tid < NOUT) s_At[tid] = At[tid];
    __syncthreads();

    const float* wblob = Wt + (size_t)rel * NC * BWF;
    const uint32_t a_s0 = smem_u32(Asm);
    const uint32_t b_s0 = smem_u32(Bsm);

    auto load_chunk = [&](int c, int buf) {
        const int k0 = c * 32;
        int seg, off;
        if (k0 < FIN)              { seg = 0; off = k0; }
        else if (k0 < FIN + EMB_)  { seg = 1; off = k0 - FIN; }
        else                       { seg = 2; off = k0 - FIN - EMB_; }
        const uint32_t ab = a_s0 + buf * AW * 4;
#pragma unroll
        for (int t = 0; t < 4; t++) {
            int i = tid + t * 256;
            int row = i >> 3, u = i & 7;
            cp_async16(ab + (row * AST) * 4 + u * 16, s_p[seg][row] + off + u * 4);
        }
        const float* wb = wblob + (size_t)c * BWF;
        const uint32_t bb = b_s0 + buf * BWF * 4;
#pragma unroll
        for (int t = 0; t < BWF / 4 / 256; t++) {
            int i = (tid + t * 256) * 4;
            cp_async16(bb + i * 4, wb + i);
        }
        asm volatile("cp.async.commit_group;" ::: "memory");
    };

    const int warp = tid >> 5, lane = tid & 31;
    const int wr = warp & 3, wc = warp >> 2;
    const int g = lane >> 2, q = lane & 3;

    float acc[2][NF][4];
#pragma unroll
    for (int mg = 0; mg < 2; mg++)
#pragma unroll
        for (int nf = 0; nf < NF; nf++)
#pragma unroll
            for (int j = 0; j < 4; j++) acc[mg][nf][j] = 0.f;

    load_chunk(0, 0);
    load_chunk(1, 1);

    for (int c = 0; c < NC; c++) {
        asm volatile("cp.async.wait_group 1;" ::: "memory");
        __syncthreads();
        if (c + 2 < NC) load_chunk(c + 2, (c + 2) % 3);
        else asm volatile("cp.async.commit_group;" ::: "memory");

        const float* ab = Asm + (c % 3) * AW;
        const float* bb = Bsm + (c % 3) * BWF;
#pragma unroll
        for (int ks = 0; ks < 4; ks++) {
            uint32_t a[2][4];
#pragma unroll
            for (int mg = 0; mg < 2; mg++) {
                const float* ap = ab + (wr * 32 + mg * 16 + g) * AST + ks * 8 + q;
                a[mg][0] = __float_as_uint(ap[0]);
                a[mg][1] = __float_as_uint(ap[8 * AST]);
                a[mg][2] = __float_as_uint(ap[4]);
                a[mg][3] = __float_as_uint(ap[8 * AST + 4]);
            }
#pragma unroll
            for (int j = 0; j < NFH; j++) {
                float4 bv = *(const float4*)(bb +
                    (((ks * 2 + wc) * NFH + j) * 32 + lane) * 4);
                uint32_t b0a = __float_as_uint(bv.x), b1a = __float_as_uint(bv.y);
                uint32_t b0b = __float_as_uint(bv.z), b1b = __float_as_uint(bv.w);
#pragma unroll
                for (int mg = 0; mg < 2; mg++) {
                    asm volatile(
                        "mma.sync.aligned.m16n8k8.row.col.f32.tf32.tf32.f32 "
                        "{%0,%1,%2,%3},{%4,%5,%6,%7},{%8,%9},{%0,%1,%2,%3};"
                        : "+f"(acc[mg][2 * j][0]), "+f"(acc[mg][2 * j][1]),
                          "+f"(acc[mg][2 * j][2]), "+f"(acc[mg][2 * j][3])
                        : "r"(a[mg][0]), "r"(a[mg][1]), "r"(a[mg][2]), "r"(a[mg][3]),
                          "r"(b0a), "r"(b1a));
                    asm volatile(
                        "mma.sync.aligned.m16n8k8.row.col.f32.tf32.tf32.f32 "
                        "{%0,%1,%2,%3},{%4,%5,%6,%7},{%8,%9},{%0,%1,%2,%3};"
                        : "+f"(acc[mg][2 * j + 1][0]), "+f"(acc[mg][2 * j + 1][1]),
                          "+f"(acc[mg][2 * j + 1][2]), "+f"(acc[mg][2 * j + 1][3])
                        : "r"(a[mg][0]), "r"(a[mg][1]), "r"(a[mg][2]), "r"(a[mg][3]),
                          "r"(b0b), "r"(b1b));
                }
            }
        }
    }
    __syncthreads();

    // ---- store m rows (streaming, dst-CSR) + fused attention logits ----
    float p0[2], p1[2];
#pragma unroll
    for (int mg = 0; mg < 2; mg++) {
        int r0 = wr * 32 + mg * 16 + g;
        int d0 = s_pos[r0], d1 = s_pos[r0 + 8];
        p0[mg] = 0.f; p1[mg] = 0.f;
#pragma unroll
        for (int nf = 0; nf < NF; nf++) {
            int col = wc * (NOUT / 2) + nf * 8 + 2 * q;
            float a0 = s_At[col], a1 = s_At[col + 1];
            p0[mg] += acc[mg][nf][0] * a0 + acc[mg][nf][1] * a1;
            p1[mg] += acc[mg][nf][2] * a0 + acc[mg][nf][3] * a1;
            if (d0 >= 0)
                st_cs_f2(g_m + (size_t)d0 * NOUT + col,
                         acc[mg][nf][0], acc[mg][nf][1]);
            if (d1 >= 0)
                st_cs_f2(g_m + (size_t)d1 * NOUT + col,
                         acc[mg][nf][2], acc[mg][nf][3]);
        }
        p0[mg] += __shfl_xor_sync(0xffffffffu, p0[mg], 1);
        p0[mg] += __shfl_xor_sync(0xffffffffu, p0[mg], 2);
        p1[mg] += __shfl_xor_sync(0xffffffffu, p1[mg], 1);
        p1[mg] += __shfl_xor_sync(0xffffffffu, p1[mg], 2);
    }
    if (wc == 0 && q == 0) {
#pragma unroll
        for (int mg = 0; mg < 2; mg++) {
            s_zr[wr * 32 + mg * 16 + g]     = p0[mg];
            s_zr[wr * 32 + mg * 16 + g + 8] = p1[mg];
        }
    }
    __syncthreads();
    if (wc == 1 && q == 0) {
#pragma unroll
        for (int mg = 0; mg < 2; mg++) {
#pragma unroll
            for (int h = 0; h < 2; h++) {
                int r = wr * 32 + mg * 16 + g + h * 8;
                int p = s_pos[r];
                if (p >= 0) {
                    float tot = s_zr[r] + (h == 0 ? p0[mg] : p1[mg]);
                    float z = zn[s_dst[r]] + tot;
                    z = (z > 0.f) ? z : 0.01f * z;
                    g_z[p] = z;
                }
            }
        }
    }
}

// ------ fused: segment softmax + streaming aggregation + final epilogue ----
template <int NOUT, bool OUT_HN>
__global__ void __launch_bounds__(256)
k_aggfinal(const float* __restrict__ sl, const float* __restrict__ b,
           float* __restrict__ out) {
    const int tid = threadIdx.x;
    const int warp = tid >> 5, lane = tid & 31;
#pragma unroll
    for (int it = 0; it < 4; it++) {
        int n = blockIdx.x * 32 + it * 8 + warp;
        if (n >= N_) continue;
        int beg = g_doff[n], cnt = g_indeg_i[n];

        float zm = -3.4e38f;
        for (int i = lane; i < cnt; i += 32) zm = fmaxf(zm, g_z[beg + i]);
#pragma unroll
        for (int o = 16; o; o >>= 1)
            zm = fmaxf(zm, __shfl_xor_sync(0xffffffffu, zm, o));

        float iv = g_inv_in[n];

        if (NOUT == 128) {
            float4 ac0 = make_float4(0.f, 0.f, 0.f, 0.f);
            float4 ac1 = make_float4(0.f, 0.f, 0.f, 0.f);
            float dn0 = 0.f, dn1 = 0.f;
            const float* mrow = g_m + (size_t)beg * 128 + lane * 4;
            int i = 0;
            for (; i + 1 < cnt; i += 2) {
                float w0 = __expf(g_z[beg + i] - zm);
                float w1 = __expf(g_z[beg + i + 1] - zm);
                float4 v0 = ld_cs_f4(mrow + (size_t)i * 128);
                float4 v1 = ld_cs_f4(mrow + (size_t)(i + 1) * 128);
                dn0 += w0; dn1 += w1;
                ac0.x += w0 * v0.x; ac0.y += w0 * v0.y;
                ac0.z += w0 * v0.z; ac0.w += w0 * v0.w;
                ac1.x += w1 * v1.x; ac1.y += w1 * v1.y;
                ac1.z += w1 * v1.z; ac1.w += w1 * v1.w;
            }
            if (i < cnt) {
                float w0 = __expf(g_z[beg + i] - zm);
                float4 v0 = ld_cs_f4(mrow + (size_t)i * 128);
                dn0 += w0;
                ac0.x += w0 * v0.x; ac0.y += w0 * v0.y;
                ac0.z += w0 * v0.z; ac0.w += w0 * v0.w;
            }
            float den = dn0 + dn1;
            float4 acc = make_float4(ac0.x + ac1.x, ac0.y + ac1.y,
                                     ac0.z + ac1.z, ac0.w + ac1.w);
            float invw = (cnt > 0) ? 1.f / den : 0.f;
            float4 lt = *(const float4*)(sl + (size_t)n * 128 + lane * 4);
            float4 bb = *(const float4*)(b + lane * 4);
            float4 r;
            r.x = fmaxf((acc.x * invw + lt.x) * iv + bb.x, 0.f);
            r.y = fmaxf((acc.y * invw + lt.y) * iv + bb.y, 0.f);
            r.z = fmaxf((acc.z * invw + lt.z) * iv + bb.z, 0.f);
            r.w = fmaxf((acc.w * invw + lt.w) * iv + bb.w, 0.f);
            if (OUT_HN) {
                float so = g_inv_out[n];
                *(float4*)(g_hn + (size_t)n * 128 + lane * 4) =
                    make_float4(r.x * so, r.y * so, r.z * so, r.w * so);
            } else {
                *(float4*)(out + (size_t)n * 128 + lane * 4) = r;
            }
        } else {
            float2 ac0 = make_float2(0.f, 0.f), ac1 = make_float2(0.f, 0.f);
            float dn0 = 0.f, dn1 = 0.f;
            const float* mrow = g_m + (size_t)beg * 64 + lane * 2;
            int i = 0;
            for (; i + 1 < cnt; i += 2) {
                float w0 = __expf(g_z[beg + i] - zm);
                float w1 = __expf(g_z[beg + i + 1] - zm);
                float2 v0 = ld_cs_f2(mrow + (size_t)i * 64);
                float2 v1 = ld_cs_f2(mrow + (size_t)(i + 1) * 64);
                dn0 += w0; dn1 += w1;
                ac0.x += w0 * v0.x; ac0.y += w0 * v0.y;
                ac1.x += w1 * v1.x; ac1.y += w1 * v1.y;
            }
            if (i < cnt) {
                float w0 = __expf(g_z[beg + i] - zm);
                float2 v0 = ld_cs_f2(mrow + (size_t)i * 64);
                dn0 += w0;
                ac0.x += w0 * v0.x; ac0.y += w0 * v0.y;
            }
            float den = dn0 + dn1;
            float2 acc = make_float2(ac0.x + ac1.x, ac0.y + ac1.y);
            float invw = (cnt > 0) ? 1.f / den : 0.f;
            float2 lt = *(const float2*)(sl + (size_t)n * 64 + lane * 2);
            float2 bb = *(const float2*)(b + lane * 2);
            float2 r;
            r.x = fmaxf((acc.x * invw + lt.x) * iv + bb.x, 0.f);
            r.y = fmaxf((acc.y * invw + lt.y) * iv + bb.y, 0.f);
            *(float2*)(out + (size_t)n * 64 + lane * 2) = r;
        }
    }
}

// ------------------------------- launcher ----------------------------------
extern "C" void kernel_launch(void* const* d_in, const int* in_sizes, int n_in,
                              void* d_out, int out_size) {
    const float* node_emb  = (const float*)d_in[0];
    const float* edge_feat = (const float*)d_in[1];
    const float* W1        = (const float*)d_in[2];
    const float* A1        = (const float*)d_in[3];
    const float* b1        = (const float*)d_in[4];
    const float* L1        = (const float*)d_in[5];
    const float* W2        = (const float*)d_in[6];
    const float* A2        = (const float*)d_in[7];
    const float* b2        = (const float*)d_in[8];
    const float* L2        = (const float*)d_in[9];
    const int*   eid       = (const int*)d_in[10];
    const int*   src       = (const int*)d_in[11];
    const int*   dst       = (const int*)d_in[12];
    float*       out       = (float*)d_out;
    (void)in_sizes; (void)n_in; (void)out_size;

    const int gE = (E_ + 255) / 256;
    const int NT = (N_ + BM - 1) / BM;

    float* d_Wt1; cudaGetSymbolAddress((void**)&d_Wt1, g_Wt1);
    float* d_Wt2; cudaGetSymbolAddress((void**)&d_Wt2, g_Wt2);
    float* d_Lf1; cudaGetSymbolAddress((void**)&d_Lf1, g_Lf1);
    float* d_Lf2; cudaGetSymbolAddress((void**)&d_Lf2, g_Lf2);
    float* d_sl1; cudaGetSymbolAddress((void**)&d_sl1, g_sl1);
    float* d_sl2; cudaGetSymbolAddress((void**)&d_sl2, g_sl2);
    float* d_zn1; cudaGetSymbolAddress((void**)&d_zn1, g_zn1);
    float* d_zn2; cudaGetSymbolAddress((void**)&d_zn2, g_zn2);

    const int DS1 = 3 * (BM * 36 + HID_ * 32) * 4;      // 104448
    const int DS2 = 3 * (BM * 36 + EMB_ * 32) * 4;      //  79872
    const int SG1 = 2 * (BM * 36 + HID_ * 32) * 4;      //  69632
    const int SG2 = 2 * (BM * 36 + EMB_ * 32) * 4;      //  53248
    cudaFuncSetAttribute(k_gemm_mma<64, 128>,
                         cudaFuncAttributeMaxDynamicSharedMemorySize, DS1);
    cudaFuncSetAttribute(k_gemm_mma<128, 64>,
                         cudaFuncAttributeMaxDynamicSharedMemorySize, DS2);
    cudaFuncSetAttribute(k_selfgemm<128>,
                         cudaFuncAttributeMaxDynamicSharedMemorySize, SG1);
    cudaFuncSetAttribute(k_selfgemm<64>,
                         cudaFuncAttributeMaxDynamicSharedMemorySize, SG2);

    // ---- prep ----
    k_zero_wfrag<<<(WT1 + WT2 + SL1F + SL2F + 255) / 256, 256>>>(W1, W2, L1, L2);
    k_selfgemm<128><<<NT, 256, SG1>>>(node_emb, d_Lf1, d_sl1);
    k_selfgemm<64><<<NT, 256, SG2>>>(node_emb, d_Lf2, d_sl2);
    k_count<<<gE, 256>>>(src, dst, eid);
    k_scan_blk<<<SCAN_NB, SCAN_BS>>>();
    k_scan_top<<<1, 64>>>();
    k_scan_addnode<<<(N_ + 7) / 8, 256>>>(node_emb, A1, A2);
    k_scatter2<<<gE, 256>>>(eid, dst);

    // ---- layer 1: FIN=64, K=192, NOUT=128 ----
    k_gemm_mma<64, 128><<<MT, 256, DS1>>>(d_Wt1, A1 + EMB_, d_zn1, src, dst,
                                          edge_feat, node_emb);
    k_aggfinal<128, true><<<(N_ + 31) / 32, 256>>>(d_sl1, b1, nullptr);

    // ---- layer 2: FIN=128, K=256, NOUT=64 ----
    k_gemm_mma<128, 64><<<MT, 256, DS2>>>(d_Wt2, A2 + EMB_, d_zn2, src, dst,
                                          edge_feat, node_emb);
    k_aggfinal<64, false><<<(N_ + 31) / 32, 256>>>(d_sl2, b2, out);
}